// round 2
// baseline (speedup 1.0000x reference)
#include <cuda_runtime.h>
#include <cstdint>

#define MAX_B    64
#define IDMAX    4096
#define NOTFOUND 0x7FFFFFFF
#define TPB_TOK  64     // tokens per gather block

// Scratch: per-graph id -> first local position table (atomicMin semantics).
__device__ int g_table[MAX_B * IDMAX];

// ---------------------------------------------------------------------------
// Kernel 1: init table + zero the graph_outputs slice of d_out (it's poisoned)
// ---------------------------------------------------------------------------
__global__ void init_kernel(float* __restrict__ graph_out, int graph_elems, int table_elems) {
    int i = blockIdx.x * blockDim.x + threadIdx.x;
    if (i < table_elems) g_table[i] = NOTFOUND;
    if (i < graph_elems) graph_out[i] = 0.0f;
}

// ---------------------------------------------------------------------------
// Kernel 2: build per-graph id -> min(local position) table
// ---------------------------------------------------------------------------
__global__ void build_table_kernel(const int* __restrict__ node_index,
                                   const int* __restrict__ ptr,
                                   int B, int N) {
    int r = blockIdx.x * blockDim.x + threadIdx.x;
    if (r >= N) return;
    if (r < ptr[0] || r >= ptr[B]) return;   // rows outside segments: dropped
    // binary search: largest b with ptr[b] <= r
    int lo = 0, hi = B - 1;
    while (lo < hi) {
        int mid = (lo + hi + 1) >> 1;
        if (ptr[mid] <= r) lo = mid; else hi = mid - 1;
    }
    int b  = lo;
    int id = node_index[r];
    if (id >= 0 && id < IDMAX) {
        atomicMin(&g_table[b * IDMAX + id], r - ptr[b]);
    }
}

// ---------------------------------------------------------------------------
// Kernel 3 (fused): pool role for blockIdx.x < pool_blocks, gather role after.
// Pool:   grid-role (B * chunks) blocks, 256 thr: float4 column accumulation.
// Gather: 64 tokens / block. Phase 1 resolves table lookups into smem,
//         phase 2: warp w copies tokens [w*8, w*8+8), 2 float4 per lane each.
// ---------------------------------------------------------------------------
__global__ void fused_pool_gather(const float* __restrict__ x,
                                  const int* __restrict__ ptr,
                                  const int* __restrict__ input_ids,
                                  float* __restrict__ seq_out,
                                  float* __restrict__ graph_out,
                                  int D, int L, int total_tokens,
                                  int chunks, int pool_blocks) {
    if ((int)blockIdx.x < pool_blocks) {
        // ---------------- pool role ----------------
        int pb = blockIdx.x;
        int b  = pb / chunks;
        int c  = pb % chunks;
        int s = ptr[b], e = ptr[b + 1];
        int size  = e - s;
        int chunk = (size + chunks - 1) / chunks;
        int r0 = s + c * chunk;
        int r1 = min(e, r0 + chunk);
        if (r0 >= r1) return;

        int nvec = D >> 2;                  // float4 per row (64 for D=256)
        int d4   = threadIdx.x & (nvec - 1);        // which float4 column
        int rsub = threadIdx.x / nvec;              // row sub-lane 0..3
        int rstep = blockDim.x / nvec;              // rows advanced per iter (4)

        float4 acc = make_float4(0.f, 0.f, 0.f, 0.f);
        for (int r = r0 + rsub; r < r1; r += rstep) {
            const float4 v = ((const float4*)(x + (size_t)r * D))[d4];
            acc.x += v.x; acc.y += v.y; acc.z += v.z; acc.w += v.w;
        }
        float* g = graph_out + (size_t)b * D + 4 * d4;
        atomicAdd(g + 0, acc.x);
        atomicAdd(g + 1, acc.y);
        atomicAdd(g + 2, acc.z);
        atomicAdd(g + 3, acc.w);
    } else {
        // ---------------- gather role ----------------
        int gb = blockIdx.x - pool_blocks;
        __shared__ int spos[TPB_TOK];
        int t0  = gb * TPB_TOK;
        int tid = threadIdx.x;

        if (tid < TPB_TOK) {
            int token = t0 + tid;
            int p = NOTFOUND;
            if (token < total_tokens) {
                int b  = token / L;
                int id = __ldg(&input_ids[token]);
                p = g_table[b * IDMAX + id];
            }
            spos[tid] = p;
        }
        __syncthreads();

        int warp = tid >> 5, lane = tid & 31;
        int nvec = D >> 2;
        const int tok_per_warp = TPB_TOK / 8;   // 8 tokens per warp

        #pragma unroll
        for (int j = 0; j < tok_per_warp; j++) {
            int lt = warp * tok_per_warp + j;
            int token = t0 + lt;
            if (token >= total_tokens) break;
            int pos = spos[lt];
            float4* dst = (float4*)(seq_out + (size_t)token * D);
            if (pos == NOTFOUND) {
                float4 z = make_float4(0.f, 0.f, 0.f, 0.f);
                for (int i = lane; i < nvec; i += 32) dst[i] = z;
            } else {
                const float4* src = (const float4*)(x + (size_t)pos * D);
                for (int i = lane; i < nvec; i += 32) dst[i] = src[i];
            }
        }
    }
}

// ---------------------------------------------------------------------------
extern "C" void kernel_launch(void* const* d_in, const int* in_sizes, int n_in,
                              void* d_out, int out_size) {
    const int*   input_ids  = (const int*)  d_in[0];   // [B, L]
    const int*   node_index = (const int*)  d_in[1];   // [N]
    const float* x          = (const float*)d_in[2];   // [N, D]
    const int*   ptr        = (const int*)  d_in[3];   // [B+1]

    int B = in_sizes[3] - 1;
    int N = in_sizes[1];
    int D = in_sizes[2] / N;
    int L = in_sizes[0] / B;
    int total_tokens = B * L;

    float* seq_out   = (float*)d_out;                             // [B*L, D]
    float* graph_out = (float*)d_out + (size_t)total_tokens * D;  // [B, D]

    // 1) init (zero graph_out, set table to NOTFOUND)
    {
        int table_elems = B * IDMAX;
        int graph_elems = B * D;
        int n = max(table_elems, graph_elems);
        init_kernel<<<(n + 255) / 256, 256>>>(graph_out, graph_elems, table_elems);
    }
    // 2) build id -> first-local-pos table
    build_table_kernel<<<(N + 255) / 256, 256>>>(node_index, ptr, B, N);
    // 3) fused pool + gather
    {
        const int CHUNKS = 32;
        int pool_blocks   = B * CHUNKS;                               // 512
        int gather_blocks = (total_tokens + TPB_TOK - 1) / TPB_TOK;   // 512
        fused_pool_gather<<<pool_blocks + gather_blocks, 256>>>(
            x, ptr, input_ids, seq_out, graph_out,
            D, L, total_tokens, CHUNKS, pool_blocks);
    }
}